// round 2
// baseline (speedup 1.0000x reference)
#include <cuda_runtime.h>
#include <cuda_bf16.h>

// LightConv1d: out[b,c,t] = sum_{k=0..6} softmax(w[h])[k] * x[b,c,t-6+k] + bias[h]
// with h = c % 16 (row-major reshape [B,C,T] -> [B*N,H,T]).
// Shapes: x [8,1024,4096] f32, weight [16,1,7] f32, bias [16] f32. Output f32 same shape as x.

#define T_LEN 4096
#define KSZ   7
#define NROWS (8 * 1024)
#define NTHREADS 256
#define NSEG 4   // 256 threads * 4 segments * 4 floats = 4096 = one full row

__global__ __launch_bounds__(NTHREADS, 8)
void lightconv1d_kernel(const float* __restrict__ x,
                        const float* __restrict__ weight,
                        const float* __restrict__ bias,
                        float* __restrict__ out)
{
    // SMEM: s[0..7] front pad (s[2..7] are the 6 causal zeros), data x[j] at s[8+j].
    // out[t] = sum_k w[k] * x[t-6+k] = sum_k w[k] * s[2 + t + k]
    __shared__ __align__(16) float s[8 + T_LEN];

    const int row = blockIdx.x;          // b*1024 + c
    const int tid = threadIdx.x;

    if (tid < 8) s[tid] = 0.0f;

    const float4* __restrict__ xf4 = reinterpret_cast<const float4*>(x + (size_t)row * T_LEN);
    float4* sf4 = reinterpret_cast<float4*>(s + 8);

    // Full row: 4 block-strided float4 segments (coalesced, MLP_p1 = 4).
    float4 v[NSEG];
    #pragma unroll
    for (int seg = 0; seg < NSEG; ++seg)
        v[seg] = xf4[tid + NTHREADS * seg];
    #pragma unroll
    for (int seg = 0; seg < NSEG; ++seg)
        sf4[tid + NTHREADS * seg] = v[seg];

    // Per-thread softmax of the 7 shared weights for this head (tiny, L1-resident).
    const int h = row & 15;              // c % 16 (1024 % 16 == 0)
    float wk[KSZ];
    float m = -1e30f;
    #pragma unroll
    for (int k = 0; k < KSZ; ++k) {
        wk[k] = __ldg(&weight[h * KSZ + k]);
        m = fmaxf(m, wk[k]);
    }
    float sum = 0.0f;
    #pragma unroll
    for (int k = 0; k < KSZ; ++k) {
        wk[k] = expf(wk[k] - m);
        sum += wk[k];
    }
    const float inv = 1.0f / sum;
    #pragma unroll
    for (int k = 0; k < KSZ; ++k) wk[k] *= inv;
    const float bv = __ldg(&bias[h]);

    __syncthreads();

    float4* of4 = reinterpret_cast<float4*>(out + (size_t)row * T_LEN);

    #pragma unroll
    for (int seg = 0; seg < NSEG; ++seg) {
        const int t0 = seg * (NTHREADS * 4) + tid * 4;

        float win[10];
        #pragma unroll
        for (int i = 0; i < 10; ++i) win[i] = s[2 + t0 + i];

        float acc0 = bv, acc1 = bv, acc2 = bv, acc3 = bv;
        #pragma unroll
        for (int k = 0; k < KSZ; ++k) {
            acc0 = fmaf(wk[k], win[k + 0], acc0);
            acc1 = fmaf(wk[k], win[k + 1], acc1);
            acc2 = fmaf(wk[k], win[k + 2], acc2);
            acc3 = fmaf(wk[k], win[k + 3], acc3);
        }
        float4 r;
        r.x = acc0; r.y = acc1; r.z = acc2; r.w = acc3;
        of4[tid + NTHREADS * seg] = r;
    }
}

extern "C" void kernel_launch(void* const* d_in, const int* in_sizes, int n_in,
                              void* d_out, int out_size)
{
    const float* x      = (const float*)d_in[0];
    const float* weight = (const float*)d_in[1];
    const float* bias   = (const float*)d_in[2];
    float* out          = (float*)d_out;

    lightconv1d_kernel<<<NROWS, NTHREADS>>>(x, weight, bias, out);
}